// round 4
// baseline (speedup 1.0000x reference)
#include <cuda_runtime.h>
#include <cuda_bf16.h>
#include <mma.h>
#include <math.h>

using namespace nvcuda;

#define NROWS   131072
#define DDIM    64
#define KCODES  512
#define QSIZE   8388608
#define ENCSIZE 67108864
#define ENC_OFF (QSIZE + 1)
#define PERP_OFF (QSIZE + 1 + ENCSIZE)

#define ROWS_PB 64            // rows per block
#define NT      128           // threads per block

// dynamic smem layout (bytes)
#define OFF_B    0            // bf16 B  [64][520]            66560
#define OFF_A    66560        // bf16 A  [64][72]              9216
#define OFF_F    75776        // f32  f  [64][65]             16640
#define OFF_STG  92416        // f32  stage [4][256]           4096
#define OFF_W2   96512        // f32  w2s[512]                 2048
#define OFF_SR   98560        // f32  Srow[64]                  256
#define OFF_H    98816        // int  hist[512]                2048
#define OFF_CND  100864       // int  cand [4][128]            2048
#define OFF_CD   102912       // f32  candD[4][128]            2048
#define OFF_CNT  104960       // int  cnt[4]                     16
#define SMEM_BYTES 104976

__device__ int    g_idx[NROWS];
__device__ int    g_counts[KCODES];
__device__ double g_loss;
__device__ float  g_w2[KCODES];
__device__ float  g_w2max;

// w2[k] = sum_i round(w[k][i]^2), sequential non-fused (mimic jnp.sum(w*w,axis=1)).
// Also: zero counters, compute max_k w2[k] for the soundness bound.
__global__ void w2_kernel(const float* __restrict__ w) {
    __shared__ float red[KCODES];
    int k = threadIdx.x;
    float s = 0.0f;
    #pragma unroll 8
    for (int i = 0; i < DDIM; ++i) {
        float v = w[k * DDIM + i];
        s = __fadd_rn(s, __fmul_rn(v, v));
    }
    g_w2[k] = s;
    g_counts[k] = 0;
    if (k == 0) g_loss = 0.0;
    red[k] = s;
    __syncthreads();
    for (int st = 256; st; st >>= 1) {
        if (k < st) red[k] = fmaxf(red[k], red[k + st]);
        __syncthreads();
    }
    if (k == 0) g_w2max = red[0];
}

// Main: bf16 WMMA approximate distances -> sound candidate filter -> exact
// fp32 sequential-chain refinement (reference-identical rounding + first-index
// tie-break) -> quantized output, loss partials, histogram.
__global__ __launch_bounds__(NT, 2)
void main_kernel(const float* __restrict__ x, const float* __restrict__ w,
                 float* __restrict__ out) {
    extern __shared__ char sm[];
    __nv_bfloat16* Bs  = (__nv_bfloat16*)(sm + OFF_B);
    __nv_bfloat16* Ab  = (__nv_bfloat16*)(sm + OFF_A);
    float*         fS  = (float*)(sm + OFF_F);
    float*         stg = (float*)(sm + OFF_STG);
    float*         w2s = (float*)(sm + OFF_W2);
    float*         Srow= (float*)(sm + OFF_SR);
    int*           hist= (int*)(sm + OFF_H);
    int*           cnd = (int*)(sm + OFF_CND);
    float*         cdd = (float*)(sm + OFF_CD);
    int*           cnt = (int*)(sm + OFF_CNT);

    int tid  = threadIdx.x;
    int lane = tid & 31;
    int wid  = tid >> 5;

    int row0 = blockIdx.x * ROWS_PB;
    int b    = row0 >> 12;
    int hw0  = row0 & 4095;            // 4096 % 64 == 0 -> b fixed per block
    const size_t xbase = (size_t)b * 262144 + hw0;

    // ---- stage x rows (fp32 + bf16) ----
    for (int idx = tid; idx < ROWS_PB * DDIM; idx += NT) {
        int c = idx >> 6, r = idx & 63;
        float v = x[xbase + (size_t)c * 4096 + r];
        fS[r * 65 + c] = v;
        Ab[r * 72 + c] = __float2bfloat16(v);
    }
    // ---- stage w transposed bf16: Bs[i][k] = bf16(w[k][i]) ----
    for (int idx = tid; idx < KCODES * DDIM; idx += NT) {
        int k = idx >> 6, i = idx & 63;
        Bs[i * 520 + k] = __float2bfloat16(w[idx]);
    }
    for (int i = tid; i < KCODES; i += NT) { w2s[i] = g_w2[i]; hist[i] = 0; }
    if (lane == 0) cnt[wid] = 0;
    __syncthreads();

    int r = tid >> 1;                  // row owned by this thread (2 threads/row)
    int h = tid & 1;                   // code-half within scan
    const float* frow = fS + r * 65;

    // S = sum(f*f): sequential, NON-fused (matches reference)
    float S = 0.0f;
    #pragma unroll
    for (int i = 0; i < DDIM; ++i) S = __fadd_rn(S, __fmul_rn(frow[i], frow[i]));
    if (h == 0) Srow[r] = S;

    // sound filter width: bf16 dot err <= 2^-8 * sqrt(S*w2max) (Cauchy-Schwarz)
    float eps = 4.0f * (sqrtf(S * g_w2max) * (1.06f / 256.0f) + 1e-6f) + 4e-5f;

    // A fragments: rows r0..r0+15 of this warp, reused across both passes
    wmma::fragment<wmma::matrix_a, 16, 16, 16, __nv_bfloat16, wmma::row_major> af[4];
    int r0 = wid * 16;
    #pragma unroll
    for (int kt = 0; kt < 4; ++kt)
        wmma::load_matrix_sync(af[kt], Ab + r0 * 72 + kt * 16, 72);

    float* mystg = stg + wid * 256;
    int scanoff  = (r & 15) * 16 + h * 8;

    // ---- pass 1: per-row min of approx score ----
    float smin = __int_as_float(0x7f800000);
    for (int n = 0; n < 32; ++n) {
        wmma::fragment<wmma::accumulator, 16, 16, 16, float> acc;
        wmma::fill_fragment(acc, 0.0f);
        #pragma unroll
        for (int kt = 0; kt < 4; ++kt) {
            wmma::fragment<wmma::matrix_b, 16, 16, 16, __nv_bfloat16, wmma::row_major> fb;
            wmma::load_matrix_sync(fb, Bs + kt * 16 * 520 + n * 16, 520);
            wmma::mma_sync(acc, af[kt], fb, acc);
        }
        wmma::store_matrix_sync(mystg, acc, 16, wmma::mem_row_major);
        __syncwarp();
        int kb0 = n * 16 + h * 8;
        float4 v0 = *(const float4*)(mystg + scanoff);
        float4 v1 = *(const float4*)(mystg + scanoff + 4);
        smin = fminf(smin, fmaf(-2.0f, v0.x, w2s[kb0 + 0]));
        smin = fminf(smin, fmaf(-2.0f, v0.y, w2s[kb0 + 1]));
        smin = fminf(smin, fmaf(-2.0f, v0.z, w2s[kb0 + 2]));
        smin = fminf(smin, fmaf(-2.0f, v0.w, w2s[kb0 + 3]));
        smin = fminf(smin, fmaf(-2.0f, v1.x, w2s[kb0 + 4]));
        smin = fminf(smin, fmaf(-2.0f, v1.y, w2s[kb0 + 5]));
        smin = fminf(smin, fmaf(-2.0f, v1.z, w2s[kb0 + 6]));
        smin = fminf(smin, fmaf(-2.0f, v1.w, w2s[kb0 + 7]));
        __syncwarp();
    }
    smin = fminf(smin, __shfl_xor_sync(0xffffffffu, smin, 1));
    float thr = smin + eps;

    // ---- pass 2: recompute scores, collect candidates ----
    for (int n = 0; n < 32; ++n) {
        wmma::fragment<wmma::accumulator, 16, 16, 16, float> acc;
        wmma::fill_fragment(acc, 0.0f);
        #pragma unroll
        for (int kt = 0; kt < 4; ++kt) {
            wmma::fragment<wmma::matrix_b, 16, 16, 16, __nv_bfloat16, wmma::row_major> fb;
            wmma::load_matrix_sync(fb, Bs + kt * 16 * 520 + n * 16, 520);
            wmma::mma_sync(acc, af[kt], fb, acc);
        }
        wmma::store_matrix_sync(mystg, acc, 16, wmma::mem_row_major);
        __syncwarp();
        int kb0 = n * 16 + h * 8;
        float4 v0 = *(const float4*)(mystg + scanoff);
        float4 v1 = *(const float4*)(mystg + scanoff + 4);
        float sv[8];
        sv[0] = fmaf(-2.0f, v0.x, w2s[kb0 + 0]);
        sv[1] = fmaf(-2.0f, v0.y, w2s[kb0 + 1]);
        sv[2] = fmaf(-2.0f, v0.z, w2s[kb0 + 2]);
        sv[3] = fmaf(-2.0f, v0.w, w2s[kb0 + 3]);
        sv[4] = fmaf(-2.0f, v1.x, w2s[kb0 + 4]);
        sv[5] = fmaf(-2.0f, v1.y, w2s[kb0 + 5]);
        sv[6] = fmaf(-2.0f, v1.z, w2s[kb0 + 6]);
        sv[7] = fmaf(-2.0f, v1.w, w2s[kb0 + 7]);
        #pragma unroll
        for (int j = 0; j < 8; ++j) {
            if (sv[j] <= thr) {
                int p = atomicAdd(&cnt[wid], 1);
                if (p < 128) cnd[wid * 128 + p] = (r << 16) | (kb0 + j);
            }
        }
        __syncwarp();
    }
    __syncwarp();
    int total = cnt[wid];
    int cntc  = total < 128 ? total : 128;

    // ---- warp-batched exact refinement: one candidate per lane ----
    for (int base = 0; base < cntc; base += 32) {
        int idx = base + lane;
        int rk  = (idx < cntc) ? cnd[wid * 128 + idx] : 0;
        int rr  = rk >> 16;
        int kk  = rk & 0xFFFF;
        const float* fr2 = fS + rr * 65;
        const float* wr2 = w + kk * DDIM;
        float a = 0.0f;
        #pragma unroll 16
        for (int i = 0; i < DDIM; ++i) a = fmaf(fr2[i], wr2[i], a);
        float d = fmaf(-2.0f, a, __fadd_rn(Srow[rr], w2s[kk]));
        if (idx < cntc) cdd[wid * 128 + idx] = d;
    }
    __syncwarp();

    // ---- per-row selection (first-index tie-break) ----
    int kb = 0;
    if (h == 0) {
        float db = __int_as_float(0x7f800000);
        kb = 0x7FFFFF;
        for (int s2 = 0; s2 < cntc; ++s2) {
            int rk = cnd[wid * 128 + s2];
            if ((rk >> 16) == r) {
                float dd = cdd[wid * 128 + s2];
                int   kk = rk & 0xFFFF;
                if (dd < db || (dd == db && kk < kb)) { db = dd; kb = kk; }
            }
        }
        if (total > 128) {   // overflow safety net: full exact scan
            db = __int_as_float(0x7f800000); kb = 0;
            for (int k = 0; k < KCODES; ++k) {
                const float* wr3 = w + k * DDIM;
                float a = 0.0f;
                #pragma unroll 16
                for (int i = 0; i < DDIM; ++i) a = fmaf(frow[i], wr3[i], a);
                float d = fmaf(-2.0f, a, __fadd_rn(S, w2s[k]));
                if (d < db) { db = d; kb = k; }
            }
        }
    }
    kb = __shfl_sync(0xffffffffu, kb, lane & ~1);

    if (h == 0) { g_idx[row0 + r] = kb; atomicAdd(&hist[kb], 1); }

    // ---- quantized output + loss partials (reference rounding) ----
    const float* wbr = w + (size_t)kb * DDIM;
    float* outp = out + xbase;
    float lsum = 0.0f;
    int c0 = h * 32;
    #pragma unroll
    for (int j = 0; j < 32; ++j) {
        int c = c0 + j;
        float fv = frow[c];
        float q  = wbr[c];
        float dd = __fsub_rn(q, fv);
        outp[(size_t)c * 4096 + r] = __fadd_rn(fv, dd);
        lsum = fmaf(dd, dd, lsum);
    }
    #pragma unroll
    for (int o = 16; o; o >>= 1) lsum += __shfl_down_sync(0xffffffffu, lsum, o);
    if (lane == 0) atomicAdd(&g_loss, (double)lsum);

    __syncthreads();
    for (int i = tid; i < KCODES; i += NT)
        if (hist[i]) atomicAdd(&g_counts[i], hist[i]);
}

// Zero-fill encodings vectorized. (enc+3) is 16B aligned.
__global__ void zfill_kernel(float* __restrict__ enc) {
    float4* p = (float4*)(enc + 3);
    const unsigned NV = (ENCSIZE - 4) / 4;
    unsigned stride = gridDim.x * blockDim.x;
    float4 z = make_float4(0.f, 0.f, 0.f, 0.f);
    for (unsigned i = blockIdx.x * blockDim.x + threadIdx.x; i < NV; i += stride)
        p[i] = z;
    if (blockIdx.x == 0 && threadIdx.x == 0) {
        enc[0] = 0.f; enc[1] = 0.f; enc[2] = 0.f; enc[ENCSIZE - 1] = 0.f;
    }
}

__global__ void ones_kernel(float* __restrict__ enc) {
    int n = blockIdx.x * 256 + threadIdx.x;
    enc[(size_t)n * KCODES + g_idx[n]] = 1.0f;
}

__global__ void final_kernel(float* __restrict__ out) {
    __shared__ double red[KCODES];
    int t = threadIdx.x;
    float p = (float)g_counts[t] * (1.0f / 131072.0f);
    float term = __fmul_rn(p, logf(__fadd_rn(p, 1e-10f)));
    red[t] = (double)term;
    __syncthreads();
    for (int s = 256; s; s >>= 1) {
        if (t < s) red[t] += red[t + s];
        __syncthreads();
    }
    if (t == 0) {
        out[PERP_OFF] = expf(-(float)red[0]);
        float m = (float)(g_loss / (double)QSIZE);
        out[QSIZE] = __fadd_rn(m, __fmul_rn(0.25f, m));
    }
}

extern "C" void kernel_launch(void* const* d_in, const int* in_sizes, int n_in,
                              void* d_out, int out_size) {
    const float* x = (const float*)d_in[0];
    const float* w = (const float*)d_in[1];
    float* out = (float*)d_out;

    cudaFuncSetAttribute(main_kernel, cudaFuncAttributeMaxDynamicSharedMemorySize,
                         SMEM_BYTES);

    w2_kernel<<<1, KCODES>>>(w);
    main_kernel<<<NROWS / ROWS_PB, NT, SMEM_BYTES>>>(x, w, out);
    zfill_kernel<<<2368, 256>>>(out + ENC_OFF);
    ones_kernel<<<NROWS / 256, 256>>>(out + ENC_OFF);
    final_kernel<<<1, KCODES>>>(out);
}

// round 5
// speedup vs baseline: 1.2716x; 1.2716x over previous
#include <cuda_runtime.h>
#include <cuda_bf16.h>
#include <math.h>
#include <stdint.h>

#define NROWS   131072
#define DDIM    64
#define KCODES  512
#define QSIZE   8388608
#define ENCSIZE 67108864
#define ENC_OFF (QSIZE + 1)
#define PERP_OFF (QSIZE + 1 + ENCSIZE)

#define ROWS_PB 64
#define NT      128

// dynamic smem layout (bytes)
#define OFF_B    0            // u32 Bpk[32][520]  (bf16 pairs, k-pair major)  66560
#define OFF_A    66560        // u32 Apk[64][36]   (bf16 pairs per row)         9216
#define OFF_F    75776        // f32 fS[64][65]                                16640
#define OFF_W2   92416        // f32 w2s[512]                                   2048
#define OFF_SR   94464        // f32 Srow[64]                                    256
#define OFF_H    94720        // int hist[512]                                  2048
#define OFF_CND  96768        // int cnd[4][128]                                2048
#define OFF_CD   98816        // f32 cdd[4][128]                                2048
#define OFF_CNT  100864       // int cnt[4]                                       16
#define OFF_KB   100880       // int kbs[64]                                     256
#define SMEM_BYTES 101136

__device__ int    g_idx[NROWS];
__device__ int    g_counts[KCODES];
__device__ double g_loss;
__device__ float  g_w2[KCODES];
__device__ float  g_w2max;

// w2[k] = sum_i round(w[k][i]^2), sequential non-fused (mimic jnp.sum(w*w,axis=1)).
__global__ void w2_kernel(const float* __restrict__ w) {
    __shared__ float red[KCODES];
    int k = threadIdx.x;
    float s = 0.0f;
    #pragma unroll 8
    for (int i = 0; i < DDIM; ++i) {
        float v = w[k * DDIM + i];
        s = __fadd_rn(s, __fmul_rn(v, v));
    }
    g_w2[k] = s;
    g_counts[k] = 0;
    if (k == 0) g_loss = 0.0;
    red[k] = s;
    __syncthreads();
    for (int st = 256; st; st >>= 1) {
        if (k < st) red[k] = fmaxf(red[k], red[k + st]);
        __syncthreads();
    }
    if (k == 0) g_w2max = red[0];
}

__device__ __forceinline__ void mma_bf16(float& c0, float& c1, float& c2, float& c3,
                                         uint32_t a0, uint32_t a1, uint32_t a2, uint32_t a3,
                                         uint32_t b0, uint32_t b1) {
    asm volatile("mma.sync.aligned.m16n8k16.row.col.f32.bf16.bf16.f32 "
                 "{%0,%1,%2,%3},{%4,%5,%6,%7},{%8,%9},{%0,%1,%2,%3};"
                 : "+f"(c0), "+f"(c1), "+f"(c2), "+f"(c3)
                 : "r"(a0), "r"(a1), "r"(a2), "r"(a3), "r"(b0), "r"(b1));
}

// Main: bf16 mma.sync approximate scores (all-register epilogue) -> sound
// candidate filter -> exact fp32 sequential-chain refinement (reference
// rounding + first-index tie-break) -> quantized out, loss, histogram.
__global__ __launch_bounds__(NT, 2)
void main_kernel(const float* __restrict__ x, const float* __restrict__ w,
                 float* __restrict__ out) {
    extern __shared__ char sm[];
    uint32_t*      Bpk = (uint32_t*)(sm + OFF_B);
    uint32_t*      Apk = (uint32_t*)(sm + OFF_A);
    __nv_bfloat16* Ab  = (__nv_bfloat16*)(sm + OFF_A);
    float*         fS  = (float*)(sm + OFF_F);
    float*         w2s = (float*)(sm + OFF_W2);
    float*         Srow= (float*)(sm + OFF_SR);
    int*           hist= (int*)(sm + OFF_H);
    int*           cnd = (int*)(sm + OFF_CND);
    float*         cdd = (float*)(sm + OFF_CD);
    int*           cnt = (int*)(sm + OFF_CNT);
    int*           kbs = (int*)(sm + OFF_KB);

    int tid  = threadIdx.x;
    int lane = tid & 31;
    int wid  = tid >> 5;
    int l4   = lane & 3;
    int lg   = lane >> 2;

    int row0 = blockIdx.x * ROWS_PB;
    int b    = row0 >> 12;
    int hw0  = row0 & 4095;
    const size_t xbase = (size_t)b * 262144 + hw0;

    // ---- stage x: fp32 rows + bf16 halves into Apk ----
    for (int idx = tid; idx < ROWS_PB * DDIM; idx += NT) {
        int c = idx >> 6, r = idx & 63;
        float v = x[xbase + (size_t)c * 4096 + r];
        fS[r * 65 + c] = v;
        Ab[r * 72 + c] = __float2bfloat16(v);
    }
    // ---- stage w transposed as bf16 pairs: Bpk[ip][k] = (w[k][2ip], w[k][2ip+1]) ----
    for (int t = tid; t < KCODES * 32; t += NT) {
        int k  = t >> 5;
        int ip = t & 31;
        float2 v = ((const float2*)w)[t];
        __nv_bfloat162 p = __floats2bfloat162_rn(v.x, v.y);
        Bpk[ip * 520 + k] = *(uint32_t*)&p;
    }
    for (int i = tid; i < KCODES; i += NT) { w2s[i] = g_w2[i]; hist[i] = 0; }
    if (lane == 0) cnt[wid] = 0;
    __syncthreads();

    // ---- S per row: sequential NON-fused (matches reference) ----
    if (tid < ROWS_PB) {
        const float* fr = fS + tid * 65;
        float S = 0.0f;
        #pragma unroll
        for (int i = 0; i < DDIM; ++i) S = __fadd_rn(S, __fmul_rn(fr[i], fr[i]));
        Srow[tid] = S;
    }
    __syncthreads();

    int r0 = wid * 16;                      // this warp's local row base
    int m_lo = r0 + lg, m_hi = m_lo + 8;

    // ---- A fragments (loaded once, conflict-free: banks 4m+kp) ----
    uint32_t af[4][4];
    #pragma unroll
    for (int kt = 0; kt < 4; ++kt) {
        int kp = kt * 8 + l4;
        af[kt][0] = Apk[m_lo * 36 + kp];
        af[kt][1] = Apk[m_hi * 36 + kp];
        af[kt][2] = Apk[m_lo * 36 + kp + 4];
        af[kt][3] = Apk[m_hi * 36 + kp + 4];
    }
    // B row pointers per kt (banks 8*l4+lg: conflict-free)
    const uint32_t* bp0[4];
    const uint32_t* bp1[4];
    #pragma unroll
    for (int kt = 0; kt < 4; ++kt) {
        bp0[kt] = Bpk + (kt * 8 + l4) * 520 + lg;
        bp1[kt] = Bpk + (kt * 8 + l4 + 4) * 520 + lg;
    }
    const float2* w2p = (const float2*)w2s + l4;

    // ---- pass 1: per-row min of approx score, all in registers ----
    float mn0 = __int_as_float(0x7f800000), mn1 = mn0;
    #pragma unroll 4
    for (int n0 = 0; n0 < KCODES; n0 += 8) {
        float c0 = 0.f, c1 = 0.f, c2 = 0.f, c3 = 0.f;
        #pragma unroll
        for (int kt = 0; kt < 4; ++kt)
            mma_bf16(c0, c1, c2, c3, af[kt][0], af[kt][1], af[kt][2], af[kt][3],
                     bp0[kt][n0], bp1[kt][n0]);
        float2 w2v = w2p[n0 >> 1];
        float s0 = fmaf(-2.0f, c0, w2v.x);
        float s1 = fmaf(-2.0f, c1, w2v.y);
        float s2 = fmaf(-2.0f, c2, w2v.x);
        float s3 = fmaf(-2.0f, c3, w2v.y);
        mn0 = fminf(mn0, fminf(s0, s1));
        mn1 = fminf(mn1, fminf(s2, s3));
    }
    // reduce over the 4 lanes sharing each row (lane%4 group)
    mn0 = fminf(mn0, __shfl_xor_sync(0xffffffffu, mn0, 1));
    mn0 = fminf(mn0, __shfl_xor_sync(0xffffffffu, mn0, 2));
    mn1 = fminf(mn1, __shfl_xor_sync(0xffffffffu, mn1, 1));
    mn1 = fminf(mn1, __shfl_xor_sync(0xffffffffu, mn1, 2));

    // sound filter width: bf16 dot err <= 2^-8 * sqrt(S*w2max) (Cauchy-Schwarz)
    float w2mx = g_w2max;
    float S_lo = Srow[m_lo], S_hi = Srow[m_hi];
    float thr0 = mn0 + 4.0f * (sqrtf(S_lo * w2mx) * (1.06f / 256.0f) + 1e-6f) + 4e-5f;
    float thr1 = mn1 + 4.0f * (sqrtf(S_hi * w2mx) * (1.06f / 256.0f) + 1e-6f) + 4e-5f;

    // ---- pass 2: recompute (identical arithmetic), collect candidates ----
    #pragma unroll 4
    for (int n0 = 0; n0 < KCODES; n0 += 8) {
        float c0 = 0.f, c1 = 0.f, c2 = 0.f, c3 = 0.f;
        #pragma unroll
        for (int kt = 0; kt < 4; ++kt)
            mma_bf16(c0, c1, c2, c3, af[kt][0], af[kt][1], af[kt][2], af[kt][3],
                     bp0[kt][n0], bp1[kt][n0]);
        float2 w2v = w2p[n0 >> 1];
        int ka = n0 + 2 * l4;
        float s0 = fmaf(-2.0f, c0, w2v.x);
        float s1 = fmaf(-2.0f, c1, w2v.y);
        float s2 = fmaf(-2.0f, c2, w2v.x);
        float s3 = fmaf(-2.0f, c3, w2v.y);
        if (s0 <= thr0) { int p = atomicAdd(&cnt[wid], 1); if (p < 128) cnd[wid*128+p] = (m_lo<<16)|ka; }
        if (s1 <= thr0) { int p = atomicAdd(&cnt[wid], 1); if (p < 128) cnd[wid*128+p] = (m_lo<<16)|(ka+1); }
        if (s2 <= thr1) { int p = atomicAdd(&cnt[wid], 1); if (p < 128) cnd[wid*128+p] = (m_hi<<16)|ka; }
        if (s3 <= thr1) { int p = atomicAdd(&cnt[wid], 1); if (p < 128) cnd[wid*128+p] = (m_hi<<16)|(ka+1); }
    }
    __syncwarp();
    int total = cnt[wid];
    int cntc  = total < 128 ? total : 128;

    // ---- warp-batched exact refinement: one candidate per lane ----
    for (int base = 0; base < cntc; base += 32) {
        int idx = base + lane;
        int rk  = (idx < cntc) ? cnd[wid * 128 + idx] : 0;
        int rr  = rk >> 16;
        int kk  = rk & 0xFFFF;
        const float* fr2 = fS + rr * 65;
        const float* wr2 = w + kk * DDIM;
        float a = 0.0f;
        #pragma unroll 16
        for (int i = 0; i < DDIM; ++i) a = fmaf(fr2[i], wr2[i], a);
        float d = fmaf(-2.0f, a, __fadd_rn(Srow[rr], w2s[kk]));
        if (idx < cntc) cdd[wid * 128 + idx] = d;
    }
    __syncwarp();

    // ---- per-row selection (first-index tie-break), lane%4==0 owns 2 rows ----
    if (l4 == 0) {
        #pragma unroll
        for (int half = 0; half < 2; ++half) {
            int m = m_lo + half * 8;
            float db = __int_as_float(0x7f800000);
            int kb = 0x7FFFFF;
            for (int s2 = 0; s2 < cntc; ++s2) {
                int rk = cnd[wid * 128 + s2];
                if ((rk >> 16) == m) {
                    float dd = cdd[wid * 128 + s2];
                    int   kk = rk & 0xFFFF;
                    if (dd < db || (dd == db && kk < kb)) { db = dd; kb = kk; }
                }
            }
            if (total > 128) {   // overflow safety net: full exact scan
                const float* fr3 = fS + m * 65;
                float Sm = Srow[m];
                db = __int_as_float(0x7f800000); kb = 0;
                for (int k = 0; k < KCODES; ++k) {
                    const float* wr3 = w + k * DDIM;
                    float a = 0.0f;
                    #pragma unroll 16
                    for (int i = 0; i < DDIM; ++i) a = fmaf(fr3[i], wr3[i], a);
                    float d = fmaf(-2.0f, a, __fadd_rn(Sm, w2s[k]));
                    if (d < db) { db = d; kb = k; }
                }
            }
            kbs[m] = kb;
            g_idx[row0 + m] = kb;
            atomicAdd(&hist[kb], 1);
        }
    }
    __syncthreads();

    // ---- quantized output + loss partials (reference rounding) ----
    int r  = tid & 63;
    int cb = tid >> 6;
    int kb = kbs[r];
    const float* frow = fS + r * 65;
    const float* wbr  = w + (size_t)kb * DDIM;
    float* outp = out + xbase;
    float lsum = 0.0f;
    #pragma unroll
    for (int j = 0; j < 32; ++j) {
        int c = cb + 2 * j;
        float fv = frow[c];
        float q  = wbr[c];
        float dd = __fsub_rn(q, fv);
        outp[(size_t)c * 4096 + r] = __fadd_rn(fv, dd);
        lsum = fmaf(dd, dd, lsum);
    }
    #pragma unroll
    for (int o = 16; o; o >>= 1) lsum += __shfl_down_sync(0xffffffffu, lsum, o);
    if (lane == 0) atomicAdd(&g_loss, (double)lsum);

    __syncthreads();
    for (int i = tid; i < KCODES; i += NT)
        if (hist[i]) atomicAdd(&g_counts[i], hist[i]);
}

// Zero-fill encodings vectorized. (enc+3) is 16B aligned.
__global__ void zfill_kernel(float* __restrict__ enc) {
    float4* p = (float4*)(enc + 3);
    const unsigned NV = (ENCSIZE - 4) / 4;
    unsigned stride = gridDim.x * blockDim.x;
    float4 z = make_float4(0.f, 0.f, 0.f, 0.f);
    for (unsigned i = blockIdx.x * blockDim.x + threadIdx.x; i < NV; i += stride)
        p[i] = z;
    if (blockIdx.x == 0 && threadIdx.x == 0) {
        enc[0] = 0.f; enc[1] = 0.f; enc[2] = 0.f; enc[ENCSIZE - 1] = 0.f;
    }
}

__global__ void ones_kernel(float* __restrict__ enc) {
    int n = blockIdx.x * 256 + threadIdx.x;
    enc[(size_t)n * KCODES + g_idx[n]] = 1.0f;
}

__global__ void final_kernel(float* __restrict__ out) {
    __shared__ double red[KCODES];
    int t = threadIdx.x;
    float p = (float)g_counts[t] * (1.0f / 131072.0f);
    float term = __fmul_rn(p, logf(__fadd_rn(p, 1e-10f)));
    red[t] = (double)term;
    __syncthreads();
    for (int s = 256; s; s >>= 1) {
        if (t < s) red[t] += red[t + s];
        __syncthreads();
    }
    if (t == 0) {
        out[PERP_OFF] = expf(-(float)red[0]);
        float m = (float)(g_loss / (double)QSIZE);
        out[QSIZE] = __fadd_rn(m, __fmul_rn(0.25f, m));
    }
}

extern "C" void kernel_launch(void* const* d_in, const int* in_sizes, int n_in,
                              void* d_out, int out_size) {
    const float* x = (const float*)d_in[0];
    const float* w = (const float*)d_in[1];
    float* out = (float*)d_out;

    cudaFuncSetAttribute(main_kernel, cudaFuncAttributeMaxDynamicSharedMemorySize,
                         SMEM_BYTES);

    w2_kernel<<<1, KCODES>>>(w);
    main_kernel<<<NROWS / ROWS_PB, NT, SMEM_BYTES>>>(x, w, out);
    zfill_kernel<<<4736, 256>>>(out + ENC_OFF);
    ones_kernel<<<NROWS / 256, 256>>>(out + ENC_OFF);
    final_kernel<<<1, KCODES>>>(out);
}